// round 1
// baseline (speedup 1.0000x reference)
#include <cuda_runtime.h>
#include <math.h>

// Problem constants
#define NB 16
#define NC 3
#define NT 600
#define HW 5184          // 72*72
#define HW4 (HW/4)       // 1296 float4 per row
#define ROWS (NB*NC*NT)  // 28800

// Scratch: spatial means, layout [b][c][t]
__device__ float g_x[ROWS];

// ---------------------------------------------------------------------------
// Kernel 1: mean over H*W for each (b,c,t) row. One block per row.
// Row data is contiguous (stride 5184 floats). Pure HBM streaming.
// ---------------------------------------------------------------------------
__global__ __launch_bounds__(256) void mean_kernel(const float* __restrict__ in,
                                                   float* __restrict__ xout) {
    const int row = blockIdx.x;
    const float4* p = reinterpret_cast<const float4*>(in) + (size_t)row * HW4;

    float s = 0.0f;
    for (int i = threadIdx.x; i < HW4; i += blockDim.x) {
        float4 v = __ldg(&p[i]);
        s += (v.x + v.y) + (v.z + v.w);
    }
    // warp reduce
    #pragma unroll
    for (int o = 16; o > 0; o >>= 1) s += __shfl_down_sync(0xffffffffu, s, o);

    __shared__ float ws[8];
    const int lane = threadIdx.x & 31;
    const int warp = threadIdx.x >> 5;
    if (lane == 0) ws[warp] = s;
    __syncthreads();
    if (warp == 0) {
        s = (lane < 8) ? ws[lane] : 0.0f;
        #pragma unroll
        for (int o = 4; o > 0; o >>= 1) s += __shfl_down_sync(0xffffffffu, s, o);
        if (lane == 0) xout[row] = s * (1.0f / (float)HW);
    }
}

// ---------------------------------------------------------------------------
// Kernel 2: per batch — Gram matrix, 3x3 symmetric eigensolve (dominant),
// projection, emit green channel. One block per batch element.
// ---------------------------------------------------------------------------
__global__ __launch_bounds__(256) void project_kernel(const float* __restrict__ x,
                                                      float* __restrict__ out) {
    const int b = blockIdx.x;
    const float* x0 = x + (size_t)b * NC * NT;
    const float* x1 = x0 + NT;
    const float* x2 = x0 + 2 * NT;

    __shared__ double gm[6];
    __shared__ float sv[3];
    if (threadIdx.x < 6) gm[threadIdx.x] = 0.0;
    __syncthreads();

    double m00 = 0, m01 = 0, m02 = 0, m11 = 0, m12 = 0, m22 = 0;
    for (int n = threadIdx.x; n < NT; n += blockDim.x) {
        double a = x0[n], c = x1[n], d = x2[n];
        m00 += a * a; m01 += a * c; m02 += a * d;
        m11 += c * c; m12 += c * d; m22 += d * d;
    }
    #pragma unroll
    for (int o = 16; o > 0; o >>= 1) {
        m00 += __shfl_down_sync(0xffffffffu, m00, o);
        m01 += __shfl_down_sync(0xffffffffu, m01, o);
        m02 += __shfl_down_sync(0xffffffffu, m02, o);
        m11 += __shfl_down_sync(0xffffffffu, m11, o);
        m12 += __shfl_down_sync(0xffffffffu, m12, o);
        m22 += __shfl_down_sync(0xffffffffu, m22, o);
    }
    if ((threadIdx.x & 31) == 0) {
        atomicAdd(&gm[0], m00); atomicAdd(&gm[1], m01); atomicAdd(&gm[2], m02);
        atomicAdd(&gm[3], m11); atomicAdd(&gm[4], m12); atomicAdd(&gm[5], m22);
    }
    __syncthreads();

    if (threadIdx.x == 0) {
        const double a00 = gm[0], a01 = gm[1], a02 = gm[2];
        const double a11 = gm[3], a12 = gm[4], a22 = gm[5];

        // Dominant eigenvalue of symmetric 3x3 (trigonometric method)
        double p1 = a01 * a01 + a02 * a02 + a12 * a12;
        double q = (a00 + a11 + a22) / 3.0;
        double p2 = (a00 - q) * (a00 - q) + (a11 - q) * (a11 - q) +
                    (a22 - q) * (a22 - q) + 2.0 * p1;
        double p = sqrt(p2 / 6.0);
        double lam = q;
        if (p > 0.0) {
            double b00 = (a00 - q) / p, b11 = (a11 - q) / p, b22 = (a22 - q) / p;
            double b01 = a01 / p, b02 = a02 / p, b12 = a12 / p;
            double detB = b00 * (b11 * b22 - b12 * b12)
                        - b01 * (b01 * b22 - b12 * b02)
                        + b02 * (b01 * b12 - b11 * b02);
            double r = 0.5 * detB;
            r = fmin(1.0, fmax(-1.0, r));
            double phi = acos(r) / 3.0;
            lam = q + 2.0 * p * cos(phi);
        }

        // Eigenvector: cross products of rows of (M - lam I), take max norm
        double r0x = a00 - lam, r0y = a01,       r0z = a02;
        double r1x = a01,       r1y = a11 - lam, r1z = a12;
        double r2x = a02,       r2y = a12,       r2z = a22 - lam;

        double c0x = r0y * r1z - r0z * r1y, c0y = r0z * r1x - r0x * r1z, c0z = r0x * r1y - r0y * r1x;
        double c1x = r1y * r2z - r1z * r2y, c1y = r1z * r2x - r1x * r2z, c1z = r1x * r2y - r1y * r2x;
        double c2x = r2y * r0z - r2z * r0y, c2y = r2z * r0x - r2x * r0z, c2z = r2x * r0y - r2y * r0x;

        double n0 = c0x * c0x + c0y * c0y + c0z * c0z;
        double n1 = c1x * c1x + c1y * c1y + c1z * c1z;
        double n2 = c2x * c2x + c2y * c2y + c2z * c2z;

        double vx, vy, vz, nn;
        if (n0 >= n1 && n0 >= n2) { vx = c0x; vy = c0y; vz = c0z; nn = n0; }
        else if (n1 >= n2)        { vx = c1x; vy = c1y; vz = c1z; nn = n1; }
        else                      { vx = c2x; vy = c2y; vz = c2z; nn = n2; }

        double scale = a00 + a11 + a22;  // trace as magnitude reference
        if (nn < 1e-24 * scale * scale * scale * scale || !(nn > 0.0)) {
            // Degenerate fallback: power iteration on M
            vx = 0.577350269189626; vy = 0.577350269189626; vz = 0.577350269189626;
            for (int it = 0; it < 256; ++it) {
                double tx = a00 * vx + a01 * vy + a02 * vz;
                double ty = a01 * vx + a11 * vy + a12 * vz;
                double tz = a02 * vx + a12 * vy + a22 * vz;
                double inv = rsqrt(tx * tx + ty * ty + tz * tz + 1e-300);
                vx = tx * inv; vy = ty * inv; vz = tz * inv;
            }
        } else {
            double inv = rsqrt(nn);
            vx *= inv; vy *= inv; vz *= inv;
        }
        sv[0] = (float)vx; sv[1] = (float)vy; sv[2] = (float)vz;
    }
    __syncthreads();

    const float s0 = sv[0], s1 = sv[1], s2 = sv[2];
    for (int n = threadIdx.x; n < NT; n += blockDim.x) {
        float a = x0[n], c = x1[n], d = x2[n];
        float dot = s0 * a + s1 * c + s2 * d;
        out[(size_t)b * NT + n] = c - s1 * dot;
    }
}

extern "C" void kernel_launch(void* const* d_in, const int* in_sizes, int n_in,
                              void* d_out, int out_size) {
    const float* batch_x = (const float*)d_in[0];
    float* out = (float*)d_out;

    float* xbuf;
    cudaGetSymbolAddress((void**)&xbuf, g_x);

    mean_kernel<<<ROWS, 256>>>(batch_x, xbuf);
    project_kernel<<<NB, 256>>>(xbuf, out);
}